// round 16
// baseline (speedup 1.0000x reference)
#include <cuda_runtime.h>
#include <cuda_bf16.h>
#include <cstdint>

#define K_COMP   8
#define L_LAT    64
#define D_DATA   256
#define N_ROWS   16384
#define B_ROWS   2048
#define ENC_OUT  1536   // 3*K*L
#define DEC_OUT  6144   // 3*K*D
#define D_SPLIT  8
#define IC_PER   (32 / D_SPLIT)    // 4 chunks per CTA
#define NB_DEC   (128 * D_SPLIT)   // 1024
#define W8_N     98304  // 32dc * 8kc * 3t * 128 u32 (8n x 64k fp8)
#define EA_N     786432
#define EB_N     589824

__device__ float    g_pred_e[B_ROWS * ENC_OUT];
__device__ float    g_h[N_ROWS * L_LAT];
__device__ uint32_t g_w8[W8_N];
__device__ uint32_t g_eA[EA_N];
__device__ uint32_t g_eB[EB_N];
__device__ float    g_accum[2];
__device__ unsigned int g_done;

typedef unsigned long long u64;

// ---- helpers -------------------------------------------------------------
__device__ __forceinline__ uint32_t bf16x2_pack(float hi, float lo) {
    uint32_t o; asm("cvt.rn.bf16x2.f32 %0, %1, %2;" : "=r"(o) : "f"(hi), "f"(lo)); return o;
}
__device__ __forceinline__ float bf16_rf(float v) {
    __nv_bfloat16 b = __float2bfloat16(v);
    return __bfloat162float(b);
}
// pack 4 floats -> 4 e4m3 bytes (v0 = lowest byte)
__device__ __forceinline__ uint32_t fp8x4_pack(float v0, float v1, float v2, float v3) {
    uint16_t lo, hi;
    asm("cvt.rn.satfinite.e4m3x2.f32 %0, %1, %2;" : "=h"(lo) : "f"(v1), "f"(v0));
    asm("cvt.rn.satfinite.e4m3x2.f32 %0, %1, %2;" : "=h"(hi) : "f"(v3), "f"(v2));
    uint32_t r; asm("mov.b32 %0, {%1, %2};" : "=r"(r) : "h"(lo), "h"(hi));
    return r;
}
__device__ __forceinline__ uint32_t smem_u32(const void* p) {
    uint32_t a;
    asm("{ .reg .u64 t; cvta.to.shared.u64 t, %1; cvt.u32.u64 %0, t; }" : "=r"(a) : "l"(p));
    return a;
}
#define SW128(b) ((b) ^ (((b) >> 3) & 0x70))

#define LDMATRIX_X4(r0, r1, r2, r3, addr)                                     \
    asm volatile("ldmatrix.sync.aligned.m8n8.x4.shared.b16 {%0,%1,%2,%3}, [%4];" \
        : "=r"(r0), "=r"(r1), "=r"(r2), "=r"(r3) : "r"(addr))

#define MMA_BF16(c, a0, a1, a2, a3, b0, b1)                                   \
    asm volatile("mma.sync.aligned.m16n8k16.row.col.f32.bf16.bf16.f32 "       \
        "{%0,%1,%2,%3}, {%4,%5,%6,%7}, {%8,%9}, {%0,%1,%2,%3};"               \
        : "+f"((c)[0]), "+f"((c)[1]), "+f"((c)[2]), "+f"((c)[3])              \
        : "r"(a0), "r"(a1), "r"(a2), "r"(a3), "r"(b0), "r"(b1))

#define MMA_FP8(c, a0, a1, a2, a3, b0, b1)                                    \
    asm volatile("mma.sync.aligned.m16n8k32.row.col.f32.e4m3.e4m3.f32 "       \
        "{%0,%1,%2,%3}, {%4,%5,%6,%7}, {%8,%9}, {%0,%1,%2,%3};"               \
        : "+f"((c)[0]), "+f"((c)[1]), "+f"((c)[2]), "+f"((c)[3])              \
        : "r"(a0), "r"(a1), "r"(a2), "r"(a3), "r"(b0), "r"(b1))

#define CP_ASYNC16(saddr, gaddr)                                              \
    asm volatile("cp.async.cg.shared.global [%0], [%1], 16;" :: "r"(saddr), "l"(gaddr))
#define CP_COMMIT() asm volatile("cp.async.commit_group;")
#define CP_WAIT(n)  asm volatile("cp.async.wait_group %0;" :: "n"(n))

__device__ __forceinline__ float block_reduce_256(float v) {
    __shared__ float red[8];
    int lane = threadIdx.x & 31, wid = threadIdx.x >> 5;
    #pragma unroll
    for (int o = 16; o > 0; o >>= 1) v += __shfl_down_sync(0xffffffffu, v, o);
    if (lane == 0) red[wid] = v;
    __syncthreads();
    if (wid == 0) {
        v = (lane < 8) ? red[lane] : 0.0f;
        #pragma unroll
        for (int o = 4; o > 0; o >>= 1) v += __shfl_down_sync(0xffffffffu, v, o);
    }
    return v;
}

// ---------------------------------------------------------------------------
// Fused prep, coalesced:
//   [0,192):   W_d -> fp8 (x8 scale) tiles via smem transpose
//   [192,3264): enc A' bf16-split pack
//   [3264,3840): enc B' bf16-split pack via smem transpose
// ---------------------------------------------------------------------------
__global__ __launch_bounds__(256) void prep_all(const float* __restrict__ Wd,
                                                const float* __restrict__ x,
                                                const float* __restrict__ We)
{
    const int b = blockIdx.x;
    const int tid = threadIdx.x;
    if (b == 0 && tid < 2) g_accum[tid] = 0.0f;
    if (b == 0 && tid == 2) g_done = 0u;

    __shared__ float sw[64][33];

    if (b < 192) {
        // block = (tkc 0..23, dcg 0..7); stage 64 k-rows x 32 cols
        const int dcg = b & 7;
        const int tkc = b >> 3;
        const int t  = tkc % 3;
        const int kc = tkc / 3;
        const int colbase = t * 2048 + kc * 256 + dcg * 32;
        {
            int row = tid >> 2, part = tid & 3;
            const float* src = Wd + row * DEC_OUT + colbase + part * 8;
            float4 v0 = *reinterpret_cast<const float4*>(src);
            float4 v1 = *reinterpret_cast<const float4*>(src + 4);
            float* d = &sw[row][part * 8];
            d[0] = v0.x; d[1] = v0.y; d[2] = v0.z; d[3] = v0.w;
            d[4] = v1.x; d[5] = v1.y; d[6] = v1.z; d[7] = v1.w;
        }
        __syncthreads();

        // emit 512 u32: idx -> (dcp, n, kw); u32 = fp8x4 of 4 consecutive k, scaled x8
        #pragma unroll
        for (int r2 = 0; r2 < 2; r2++) {
            int idx = tid + r2 * 256;
            int kw  = idx & 15;
            int n   = (idx >> 4) & 7;
            int dcp = idx >> 7;
            const int dc = dcg * 4 + dcp;
            const int tile = (dc * 8 + kc) * 3 + t;
            int col = dcp * 8 + n;
            g_w8[tile * 128 + n * 16 + kw] = fp8x4_pack(
                sw[4 * kw + 0][col] * 8.0f, sw[4 * kw + 1][col] * 8.0f,
                sw[4 * kw + 2][col] * 8.0f, sw[4 * kw + 3][col] * 8.0f);
        }
    } else if (b < 3264) {
        int i = (b - 192) * 256 + tid;
        int row = i / 384, j = i % 384;
        int k0 = 2 * j;
        float v0, v1;
        if (k0 < 512) {
            v0 = bf16_rf(x[row * 256 + (k0 & 255)]);
            v1 = bf16_rf(x[row * 256 + ((k0 + 1) & 255)]);
        } else {
            float a0 = x[row * 256 + (k0 - 512)];
            float a1 = x[row * 256 + (k0 - 511)];
            v0 = a0 - bf16_rf(a0);
            v1 = a1 - bf16_rf(a1);
        }
        g_eA[i] = bf16x2_pack(v1, v0);
    } else {
        const int bb = b - 3264;
        const int kc = bb / 48;
        const int cg = bb % 48;
        const int kbase = (kc < 4) ? kc * 64 : (kc < 8) ? (kc - 4) * 64 : (kc - 8) * 64;
        const bool lo = (kc >= 4) && (kc < 8);
        {
            int row = tid >> 2, part = tid & 3;
            const float* src = We + (kbase + row) * ENC_OUT + cg * 32 + part * 8;
            float4 v0 = *reinterpret_cast<const float4*>(src);
            float4 v1 = *reinterpret_cast<const float4*>(src + 4);
            float t0[8] = {v0.x, v0.y, v0.z, v0.w, v1.x, v1.y, v1.z, v1.w};
            float* d = &sw[row][part * 8];
            #pragma unroll
            for (int j = 0; j < 8; j++)
                d[j] = lo ? (t0[j] - bf16_rf(t0[j])) : bf16_rf(t0[j]);
        }
        __syncthreads();

        const int n  = tid >> 5;
        const int kp = tid & 31;
        #pragma unroll
        for (int ntp = 0; ntp < 4; ntp++) {
            const int nt = cg * 4 + ntp;
            const int r = kc * 192 + nt;
            float w0 = sw[2 * kp][ntp * 8 + n];
            float w1 = sw[2 * kp + 1][ntp * 8 + n];
            g_eB[r * 256 + tid] = bf16x2_pack(w1, w0);
        }
    }
}

// ---------------------------------------------------------------------------
// Encoder GEMM (tensor core, split-bf16 K=768): pred_e = A' @ B' + b_e
// ---------------------------------------------------------------------------
__global__ __launch_bounds__(256, 3) void enc_tc(const float* __restrict__ be)
{
    extern __shared__ uint32_t esm[];
    const uint32_t sA0 = smem_u32(esm);
    const uint32_t sA1 = sA0 + 16384;
    const uint32_t sB0 = sA1 + 16384;
    const uint32_t sB1 = sB0 + 8192;

    const int tid  = threadIdx.x;
    const int lane = tid & 31;
    const int warp = tid >> 5;
    const int bn = blockIdx.x * 64, bm = blockIdx.y * 128;
    const int nt0 = blockIdx.x * 8;

    {
        #pragma unroll
        for (int t = 0; t < 4; t++) {
            int u = tid + t * 256;
            int row = u >> 3, gg = u & 7;
            CP_ASYNC16(sA0 + SW128(row * 128 + gg * 16),
                       g_eA + (uint32_t)(bm + row) * 384 + gg * 4);
        }
        #pragma unroll
        for (int t = 0; t < 2; t++) {
            int u = tid + t * 256;
            CP_ASYNC16(sB0 + (uint32_t)(u >> 6) * 1024 + SW128((u & 63) * 16),
                       g_eB + (uint32_t)(nt0 + (u >> 6)) * 256 + (u & 63) * 4);
        }
        CP_COMMIT();
    }

    float c[8][4];
    #pragma unroll
    for (int nt = 0; nt < 8; nt++)
        #pragma unroll
        for (int p = 0; p < 4; p++) c[nt][p] = 0.0f;

    const int m0 = warp * 16;
    const int ar = m0 + ((lane >> 3) & 1) * 8 + (lane & 7);
    const uint32_t akoff = ((lane >> 4) & 1) * 16;
    const uint32_t boff = (uint32_t)(lane & 7) * 128 + (uint32_t)(lane >> 3) * 16;

    for (int kc = 0; kc < 12; kc++) {
        const uint32_t curA = (kc & 1) ? sA1 : sA0;
        const uint32_t curB = (kc & 1) ? sB1 : sB0;

        if (kc < 11) {
            const uint32_t nA = (kc & 1) ? sA0 : sA1;
            const uint32_t nB = (kc & 1) ? sB0 : sB1;
            #pragma unroll
            for (int t = 0; t < 4; t++) {
                int u = tid + t * 256;
                int row = u >> 3, gg = u & 7;
                CP_ASYNC16(nA + SW128(row * 128 + gg * 16),
                           g_eA + (uint32_t)(bm + row) * 384 + (kc + 1) * 32 + gg * 4);
            }
            #pragma unroll
            for (int t = 0; t < 2; t++) {
                int u = tid + t * 256;
                CP_ASYNC16(nB + (uint32_t)(u >> 6) * 1024 + SW128((u & 63) * 16),
                           g_eB + ((uint32_t)(kc + 1) * 192 + nt0 + (u >> 6)) * 256 + (u & 63) * 4);
            }
            CP_COMMIT();
            CP_WAIT(1);
        } else {
            CP_WAIT(0);
        }
        __syncthreads();

        uint32_t afr[4][4];
        #pragma unroll
        for (int s = 0; s < 4; s++) {
            uint32_t off = (uint32_t)ar * 128 + s * 32 + akoff;
            LDMATRIX_X4(afr[s][0], afr[s][1], afr[s][2], afr[s][3], curA + SW128(off));
        }

        #pragma unroll
        for (int nt = 0; nt < 8; nt++) {
            const uint32_t tb = curB + nt * 1024;
            #pragma unroll
            for (int s2 = 0; s2 < 2; s2++) {
                uint32_t b0, b1, b2, b3;
                LDMATRIX_X4(b0, b1, b2, b3, tb + SW128(boff + s2 * 64));
                MMA_BF16(c[nt], afr[2*s2][0], afr[2*s2][1], afr[2*s2][2], afr[2*s2][3], b0, b1);
                MMA_BF16(c[nt], afr[2*s2+1][0], afr[2*s2+1][1], afr[2*s2+1][2], afr[2*s2+1][3], b2, b3);
            }
        }
        __syncthreads();
    }

    const int g8 = lane >> 2;
    const int c2 = (lane & 3) * 2;
    const int r0 = bm + m0 + g8, r1 = r0 + 8;
    #pragma unroll
    for (int nt = 0; nt < 8; nt++) {
        int col = bn + nt * 8 + c2;
        float b0 = be[col], b1 = be[col + 1];
        g_pred_e[r0 * ENC_OUT + col]     = c[nt][0] + b0;
        g_pred_e[r0 * ENC_OUT + col + 1] = c[nt][1] + b1;
        g_pred_e[r1 * ENC_OUT + col]     = c[nt][2] + b0;
        g_pred_e[r1 * ENC_OUT + col + 1] = c[nt][3] + b1;
    }
}

// ---------------------------------------------------------------------------
// Sampling + h + (L_q - L_e) partials, replica-folded. fp32.
// ---------------------------------------------------------------------------
__global__ __launch_bounds__(256) void sample_k(const float* __restrict__ ue,
                                                const float* __restrict__ rr)
{
    const int l  = threadIdx.x & 63;
    const int rb = threadIdx.x >> 6;
    const int br = blockIdx.x * 4 + rb;
    const float* row = g_pred_e + br * ENC_OUT;

    float m[K_COMP], ep[K_COMP], q[K_COMP], c[K_COMP];

    float a[K_COMP], e[K_COMP];
    float amax = -1e30f;
    #pragma unroll
    for (int k = 0; k < K_COMP; k++) {
        a[k] = row[1024 + k * 64 + l];
        amax = fmaxf(amax, a[k]);
    }
    float s = 0.0f;
    #pragma unroll
    for (int k = 0; k < K_COMP; k++) { e[k] = __expf(a[k] - amax); s += e[k]; }
    const float lse_a = amax + __logf(s);
    const float inv = 1.0f / s;
    {
        float cc = 0.0f;
        #pragma unroll
        for (int k = 0; k < K_COMP; k++) { cc += e[k] * inv; c[k] = cc; }
    }
    #pragma unroll
    for (int k = 0; k < K_COMP; k++) {
        m[k]  = row[k * 64 + l];
        float p = row[512 + k * 64 + l];
        ep[k] = __expf(p);
        q[k]  = a[k] - lse_a + 0.5f * p;
    }

    float part = 0.0f;

    #pragma unroll
    for (int j = 0; j < 8; j++) {
        const int n = br + 2048 * j;
        const float rv = rr[n * 64 + l];

        float msel = m[0], esel = ep[0];
        #pragma unroll
        for (int k = 1; k < K_COMP; k++) {
            bool g = rv > c[k - 1];
            msel = g ? m[k]  : msel;
            esel = g ? ep[k] : esel;
        }

        const float hv = msel + rsqrtf(esel) * ue[n * 64 + l];
        g_h[n * 64 + l] = hv;

        float st = 0.0f;
        #pragma unroll
        for (int k = 0; k < K_COMP; k++) {
            float dd = hv - m[k];
            st += __expf(q[k] - 0.5f * ep[k] * dd * dd);
        }
        part += -0.5f * hv * hv - __logf(st);
    }

    part = block_reduce_256(part);
    if (threadIdx.x == 0) atomicAdd(&g_accum[0], part);
}

// ---------------------------------------------------------------------------
// Decoder: FP8 (e4m3) tensor-core GEMM + fused mixture epilogue + fused final.
// Grid 1024 = 128 M-tiles(128 rows) x 8 d-eighths (4 chunks each).
// Per kc: 3 LDSM + 6 MMA(m16n8k32). W pre-scaled x8; epilogue multiplies 0.125.
// fp8 tile rows = 64B, packed two-per-128B line under SW128.
// Smem: B dbl 2x12KB (h tile 8KB staged inside buf1) = 24KB.
// ---------------------------------------------------------------------------
__global__ __launch_bounds__(256, 3) void dec_k(const float* __restrict__ x,
                                                const float* __restrict__ bd,
                                                float* __restrict__ out)
{
    extern __shared__ uint32_t dsm[];
    uint32_t* bufB = dsm;                       // [0, 6144) u32 : 2x12KB
    uint32_t* hsm  = dsm + 3072;                // h fp8 tile inside bufB[1]

    const int tid  = threadIdx.x;
    const int lane = tid & 31;
    const int warp = tid >> 5;
    const int mt   = blockIdx.x & 127;
    const int ds   = blockIdx.x >> 7;
    const int row0 = mt * 128;
    const int dc0  = ds * IC_PER;

    const uint32_t sb_bufB = smem_u32(bufB);
    const uint32_t sb_h    = smem_u32(hsm);

    // stage h tile (128 rows x 64 fp8 = 8KB) into bufB[1] space
    // thread -> (r = tid>>1, half = tid&1): 8 u32 of 4 fp8 each
    {
        int r = tid >> 1, hf = tid & 1;
        const float* hp = g_h + (row0 + r) * 64 + hf * 32;
        const uint32_t rowbase = (uint32_t)(r >> 1) * 128 + (uint32_t)(r & 1) * 64 + hf * 32;
        #pragma unroll
        for (int j = 0; j < 8; j++) {
            float4 v = *reinterpret_cast<const float4*>(hp + 4 * j);
            hsm[SW128(rowbase + 4 * j) >> 2] = fp8x4_pack(v.x, v.y, v.z, v.w);
        }
    }

    // prefetch d-chunk dc0 into bufB[0]: 768 x 16B chunks, 3 per thread
    {
        const uint32_t* gsrc = g_w8 + dc0 * 3072;
        #pragma unroll
        for (int j = 0; j < 3; j++) {
            int c = tid + j * 256;
            int tile = c >> 5, w = c & 31;
            int n = w >> 2, c16 = w & 3;
            uint32_t so = (uint32_t)tile * 512 + (uint32_t)(n >> 1) * 128
                        + (uint32_t)(n & 1) * 64 + (uint32_t)c16 * 16;
            CP_ASYNC16(sb_bufB + SW128(so), gsrc + tile * 128 + n * 16 + c16 * 4);
        }
        CP_COMMIT();
    }
    __syncthreads();

    // A fragments (this warp's 16 rows, K=64 fp8 -> 2 k32 steps)
    uint32_t afr[2][4];
    {
        const int m0 = warp * 16;
        const int r = m0 + ((lane >> 3) & 1) * 8 + (lane & 7);
        const uint32_t rowbase = (uint32_t)(r >> 1) * 128 + (uint32_t)(r & 1) * 64
                               + ((lane >> 4) & 1) * 16;
        #pragma unroll
        for (int s = 0; s < 2; s++) {
            LDMATRIX_X4(afr[s][0], afr[s][1], afr[s][2], afr[s][3],
                        sb_h + SW128(rowbase + s * 32));
        }
    }
    __syncthreads();   // all afr loads complete before bufB[1] is overwritten

    // epilogue geometry
    const int g8  = lane >> 2;
    const int c2  = (lane & 3) * 2;
    const int xr0 = (row0 + warp * 16 + g8) & (B_ROWS - 1);
    const int xr1 = (row0 + warp * 16 + g8 + 8) & (B_ROWS - 1);
    const uint32_t bo = (uint32_t)((lane & 7) >> 1) * 128 + (uint32_t)(lane & 1) * 64
                      + (uint32_t)(lane >> 3) * 16;

    float part = 0.0f;

    for (int ic = 0; ic < IC_PER; ic++) {
        const int dc = dc0 + ic;
        const uint32_t curB = sb_bufB + (ic & 1) * 12288;

        if (ic < IC_PER - 1) {
            const uint32_t* gsrc = g_w8 + (dc + 1) * 3072;
            const uint32_t nxtB = sb_bufB + ((ic + 1) & 1) * 12288;
            #pragma unroll
            for (int j = 0; j < 3; j++) {
                int c = tid + j * 256;
                int tile = c >> 5, w = c & 31;
                int n = w >> 2, c16 = w & 3;
                uint32_t so = (uint32_t)tile * 512 + (uint32_t)(n >> 1) * 128
                            + (uint32_t)(n & 1) * 64 + (uint32_t)c16 * 16;
                CP_ASYNC16(nxtB + SW128(so), gsrc + tile * 128 + n * 16 + c16 * 4);
            }
            CP_COMMIT();
            CP_WAIT(1);
        } else {
            CP_WAIT(0);
        }
        __syncthreads();

        const int d0 = dc * 8 + c2;
        float2 x0 = *reinterpret_cast<const float2*>(x + xr0 * D_DATA + d0);
        float2 x1 = *reinterpret_cast<const float2*>(x + xr1 * D_DATA + d0);

        float s_t[4] = {0.f, 0.f, 0.f, 0.f};
        float s_a[4] = {0.f, 0.f, 0.f, 0.f};

        #pragma unroll
        for (int kc = 0; kc < K_COMP; kc++) {
            float cm[4] = {0.f, 0.f, 0.f, 0.f};
            float cp_[4] = {0.f, 0.f, 0.f, 0.f};
            float ca[4] = {0.f, 0.f, 0.f, 0.f};

            const uint32_t tb = (uint32_t)kc * 1536;
            uint32_t b0, b1, b2, b3;
            // type 0 (m)
            LDMATRIX_X4(b0, b1, b2, b3, curB + SW128(tb + 0 + bo));
            MMA_FP8(cm, afr[0][0], afr[0][1], afr[0][2], afr[0][3], b0, b1);
            MMA_FP8(cm, afr[1][0], afr[1][1], afr[1][2], afr[1][3], b2, b3);
            // type 1 (logp)
            LDMATRIX_X4(b0, b1, b2, b3, curB + SW128(tb + 512 + bo));
            MMA_FP8(cp_, afr[0][0], afr[0][1], afr[0][2], afr[0][3], b0, b1);
            MMA_FP8(cp_, afr[1][0], afr[1][1], afr[1][2], afr[1][3], b2, b3);
            // type 2 (loga)
            LDMATRIX_X4(b0, b1, b2, b3, curB + SW128(tb + 1024 + bo));
            MMA_FP8(ca, afr[0][0], afr[0][1], afr[0][2], afr[0][3], b0, b1);
            MMA_FP8(ca, afr[1][0], afr[1][1], afr[1][2], afr[1][3], b2, b3);

            const int bi = kc * 256 + d0;
            float2 bm2 = __ldg(reinterpret_cast<const float2*>(bd + bi));
            float2 bp2 = __ldg(reinterpret_cast<const float2*>(bd + 2048 + bi));
            float2 ba2 = __ldg(reinterpret_cast<const float2*>(bd + 4096 + bi));

            #pragma unroll
            for (int p = 0; p < 4; p++) {
                float bm = (p & 1) ? bm2.y : bm2.x;
                float bp = (p & 1) ? bp2.y : bp2.x;
                float ba = (p & 1) ? ba2.y : ba2.x;
                float xval = (p == 0) ? x0.x : (p == 1) ? x0.y : (p == 2) ? x1.x : x1.y;
                float m  = cm[p] * 0.125f + bm;
                float pv = cp_[p] * 0.125f + bp;
                float av = ca[p] * 0.125f + ba;
                float dd = xval - m;
                float tt = av + 0.5f * pv - 0.5f * __expf(pv) * dd * dd;
                s_t[p] += __expf(tt);
                s_a[p] += __expf(av);
            }
        }

        #pragma unroll
        for (int p = 0; p < 4; p++)
            part += __logf(s_t[p]) - __logf(s_a[p]);

        __syncthreads();   // all curB reads done before it is refilled (ic+2)
    }

    // block reduce + last-CTA final transform
    {
        __shared__ float red[8];
        #pragma unroll
        for (int o = 16; o > 0; o >>= 1) part += __shfl_down_sync(0xffffffffu, part, o);
        if (lane == 0) red[warp] = part;
        __syncthreads();
        if (tid == 0) {
            float s = 0.0f;
            #pragma unroll
            for (int w = 0; w < 8; w++) s += red[w];
            atomicAdd(&g_accum[1], s);
            __threadfence();
            unsigned int v = atomicAdd(&g_done, 1u);
            if (v == NB_DEC - 1) {
                const float c2f = -0.5f * 256.0f * 1.8378770664093453f;
                out[0] = -((g_accum[0] + g_accum[1]) / (float)N_ROWS + c2f);
            }
        }
    }
}

extern "C" void kernel_launch(void* const* d_in, const int* in_sizes, int n_in,
                              void* d_out, int out_size) {
    const float* x  = (const float*)d_in[0];
    const float* We = (const float*)d_in[1];
    const float* be = (const float*)d_in[2];
    const float* Wd = (const float*)d_in[3];
    const float* bd = (const float*)d_in[4];
    const float* ue = (const float*)d_in[5];
    const float* rr = (const float*)d_in[6];
    float* out = (float*)d_out;

    static bool attr_set = false;
    if (!attr_set) {
        cudaFuncSetAttribute(dec_k, cudaFuncAttributeMaxDynamicSharedMemorySize, 24576);
        cudaFuncSetAttribute(enc_tc, cudaFuncAttributeMaxDynamicSharedMemorySize, 49152);
        attr_set = true;
    }

    prep_all<<<3840, 256>>>(Wd, x, We);
    enc_tc<<<dim3(24, 16), 256, 49152>>>(be);
    sample_k<<<512, 256>>>(ue, rr);
    dec_k<<<NB_DEC, 256, 24576>>>(x, bd, out);
}